// round 8
// baseline (speedup 1.0000x reference)
#include <cuda_runtime.h>
#include <cstdint>

#define B_ 8
#define S_ 4096
#define D_ 1024
#define L_ 16

#define TR    16            // tile rows (s) per stage
#define NT    16            // tiles per CTA -> 256 rows/CTA
#define CTAB  16            // CTAs per batch
#define GRID  (B_*CTAB)     // 128
#define THR   256
#define TP    1028          // tile pitch (floats): 4*row+col distinct banks for scores-B
#define SP    1028          // summ pitch
#define EP    20            // e-minus-1 staging pitch
#define RP    18            // score-reduce pitch

// smem offsets (floats)
#define OFF_T1 (TR*TP)                 // 16448 (buffer 1)
#define OFF_SU (2*TR*TP)               // 32896
#define OFF_ES (OFF_SU + L_*SP)        // 49344
#define OFF_RD (OFF_ES + L_*EP)        // 49664
#define OFF_ZB (OFF_RD + 8*L_*RP)      // 51968
#define SMEM_FLOATS (OFF_ZB + L_*RP)   // 52256
#define SMEM_BYTES  (SMEM_FLOATS*4)    // 209,024 B

// scratch (allocation-free rule)
__device__ float g_G[(size_t)GRID*L_*D_];   // per-CTA ctx partials (8 MB)
__device__ float g_cs[GRID*D_];             // per-CTA column sums  (512 KB)
__device__ float g_z[GRID*L_];              // per-CTA sum(e-1)

__device__ __forceinline__ void cpa16(uint32_t saddr, const void* gaddr) {
    asm volatile("cp.async.ca.shared.global [%0], [%1], 16;\n" :: "r"(saddr), "l"(gaddr));
}
__device__ __forceinline__ void mma_tf32(float* c, const float* a, const float* b) {
    asm volatile(
        "mma.sync.aligned.m16n8k8.row.col.f32.tf32.tf32.f32 "
        "{%0,%1,%2,%3}, {%4,%5,%6,%7}, {%8,%9}, {%0,%1,%2,%3};\n"
        : "+f"(c[0]), "+f"(c[1]), "+f"(c[2]), "+f"(c[3])
        : "f"(a[0]), "f"(a[1]), "f"(a[2]), "f"(a[3]), "f"(b[0]), "f"(b[1]));
}

// ---------------------------------------------------------------------------
// Fused kernel: per 16-row tile -> scores MMA (k=1024), e, ctx MMA (k=16)
// accumulating G[16 x 1024] in registers; memory is read exactly once.
// ---------------------------------------------------------------------------
__global__ void __launch_bounds__(THR, 1)
kMain(const float* __restrict__ mem, const float* __restrict__ summ) {
    extern __shared__ float sA[];
    const int t    = threadIdx.x;
    const int bx   = blockIdx.x;
    const int warp = t >> 5;
    const int lane = t & 31;
    const int g    = lane >> 2;
    const int tig  = lane & 3;
    const uint32_t sbase = (uint32_t)__cvta_generic_to_shared(sA);

    // stage summarizer -> padded smem (first consumer is after a syncthreads)
    for (int i = t; i < L_*D_; i += THR)
        sA[OFF_SU + (i >> 10)*SP + (i & 1023)] = summ[i];

    const int b     = bx >> 4;
    const int row0  = (bx & 15) * (TR*NT);
    const float* gbase = mem + ((size_t)b*S_ + row0)*D_;

    const int sr = t >> 4;            // staging row 0..15
    const int sc = (t & 15) * 4;      // staging col

#define STAGE(i, buf) do {                                                     \
        const float* gp = gbase + ((size_t)((i)*TR + sr))*D_ + sc;             \
        uint32_t sp = sbase + 4u*((buf)*(TR*TP) + sr*TP + sc);                 \
        _Pragma("unroll")                                                      \
        for (int k = 0; k < 16; ++k) cpa16(sp + 4u*64*k, gp + 64*k);           \
        asm volatile("cp.async.commit_group;\n" ::: "memory");                 \
    } while (0)

    float gacc[16][4];
#pragma unroll
    for (int nt = 0; nt < 16; ++nt) { gacc[nt][0]=0.f; gacc[nt][1]=0.f; gacc[nt][2]=0.f; gacc[nt][3]=0.f; }
    float colacc[4] = {0.f, 0.f, 0.f, 0.f};
    float zacc = 0.f;
    const int lo = t >> 4, jo = t & 15;

    STAGE(0, 0);

    for (int it = 0; it < NT; ++it) {
        if (it + 1 < NT) {
            STAGE(it + 1, (it + 1) & 1);
            asm volatile("cp.async.wait_group 1;\n" ::: "memory");
        } else {
            asm volatile("cp.async.wait_group 0;\n" ::: "memory");
        }
        __syncthreads();

        const float* tile = sA + (it & 1)*(TR*TP);

        // ---- scores MMA: warp owns k-slice [128w,128w+128) of D ----
        float s0[4] = {0.f,0.f,0.f,0.f}, s1[4] = {0.f,0.f,0.f,0.f};
#pragma unroll
        for (int ks = 0; ks < 16; ++ks) {
            const int k0 = warp*128 + ks*8;
            float a[4];
            a[0] = sA[OFF_SU + g*SP     + k0 + tig];
            a[1] = sA[OFF_SU + (g+8)*SP + k0 + tig];
            a[2] = sA[OFF_SU + g*SP     + k0 + tig + 4];
            a[3] = sA[OFF_SU + (g+8)*SP + k0 + tig + 4];
            float b0[2], b1[2];
            b0[0] = tile[g*TP     + k0 + tig];
            b0[1] = tile[g*TP     + k0 + tig + 4];
            b1[0] = tile[(8+g)*TP + k0 + tig];
            b1[1] = tile[(8+g)*TP + k0 + tig + 4];
            mma_tf32(s0, a, b0);
            mma_tf32(s1, a, b1);
        }
        {   // cross-warp reduce staging
            float* red = sA + OFF_RD + warp*(L_*RP);
            *(float2*)&red[g*RP     + 2*tig]     = make_float2(s0[0], s0[1]);
            *(float2*)&red[(g+8)*RP + 2*tig]     = make_float2(s0[2], s0[3]);
            *(float2*)&red[g*RP     + 8 + 2*tig] = make_float2(s1[0], s1[1]);
            *(float2*)&red[(g+8)*RP + 8 + 2*tig] = make_float2(s1[2], s1[3]);
        }
        __syncthreads();

        // ---- e-1: thread (lo, jo) ----
        {
            float scv = 0.f;
#pragma unroll
            for (int w = 0; w < 8; ++w) scv += sA[OFF_RD + w*(L_*RP) + lo*RP + jo];
            float em1 = __expf(scv * 0.03125f) - 1.0f;   // scores ~O(0.05)
            sA[OFF_ES + lo*EP + jo] = em1;
            zacc += em1;
        }
        __syncthreads();

        // ---- ctx MMA: G[l, d-slice] += (e-1) @ tile ; warp owns d [128w,+128) ----
#pragma unroll
        for (int ksx = 0; ksx < 2; ++ksx) {
            const int k0 = ksx*8;
            float a[4];
            a[0] = sA[OFF_ES + g*EP     + k0 + tig];
            a[1] = sA[OFF_ES + (g+8)*EP + k0 + tig];
            a[2] = sA[OFF_ES + g*EP     + k0 + tig + 4];
            a[3] = sA[OFF_ES + (g+8)*EP + k0 + tig + 4];
#pragma unroll
            for (int nt = 0; nt < 16; ++nt) {
                const int n0 = warp*128 + nt*8;
                float bfr[2];
                bfr[0] = tile[(k0+tig)*TP   + n0 + g];
                bfr[1] = tile[(k0+tig+4)*TP + n0 + g];
                mma_tf32(gacc[nt], a, bfr);
            }
        }

        // ---- column sums (exact fp32): thread owns d = 4t..4t+3 ----
#pragma unroll
        for (int r = 0; r < TR; ++r) {
            float4 v = *(const float4*)&tile[r*TP + 4*t];
            colacc[0] += v.x; colacc[1] += v.y; colacc[2] += v.z; colacc[3] += v.w;
        }
        __syncthreads();    // all warps done with this buffer before restage
    }
#undef STAGE

    // ---- epilogue: write partials ----
    *(float4*)&g_cs[bx*D_ + 4*t] = make_float4(colacc[0], colacc[1], colacc[2], colacc[3]);

    sA[OFF_ZB + lo*RP + jo] = zacc;
    __syncthreads();
    if (t < L_) {
        float z = 0.f;
#pragma unroll
        for (int j = 0; j < 16; ++j) z += sA[OFF_ZB + t*RP + j];
        g_z[bx*L_ + t] = z;             // sum of (e-1); +S added in kF
    }

#pragma unroll
    for (int nt = 0; nt < 16; ++nt) {
        const int d0 = warp*128 + nt*8 + 2*tig;
        *(float2*)&g_G[((size_t)bx*L_ + g    )*D_ + d0] = make_float2(gacc[nt][0], gacc[nt][1]);
        *(float2*)&g_G[((size_t)bx*L_ + g + 8)*D_ + d0] = make_float2(gacc[nt][2], gacc[nt][3]);
    }
}

// ---------------------------------------------------------------------------
// Reduce kernel: out[b,d] = C0*colsum[b,d] + sum_l c_bl * G[b,l,d]
// grid 128 = 8 batches x 16 d-chunks(64); 4 j-groups per block.
// ---------------------------------------------------------------------------
__global__ void __launch_bounds__(THR, 2)
kF(const float* __restrict__ wproj, float* __restrict__ out) {
    const int t  = threadIdx.x;
    const int bx = blockIdx.x;
    const int b  = bx >> 4;
    const int d  = (bx & 15)*64 + (t & 63);
    const int jg = t >> 6;                 // 0..3

    __shared__ float cl[L_];
    __shared__ float C0s;
    __shared__ float sred[4][64];

    if (t < L_) {
        float Z = (float)S_;
#pragma unroll
        for (int j = 0; j < CTAB; ++j) Z += g_z[(b*CTAB + j)*L_ + t];
        cl[t] = wproj[t] / Z;
    }
    __syncthreads();
    if (t == 0) {
        float c0 = 0.f;
#pragma unroll
        for (int l = 0; l < L_; ++l) c0 += cl[l];
        C0s = c0;
    }
    __syncthreads();

    float pacc = 0.f;
#pragma unroll
    for (int jj = 0; jj < 4; ++jj) {
        const int j = jg*4 + jj;
        pacc += C0s * g_cs[(b*CTAB + j)*D_ + d];
        const float* Gp = &g_G[((size_t)(b*CTAB + j))*L_*D_ + d];
#pragma unroll
        for (int l = 0; l < L_; ++l) pacc += cl[l] * Gp[(size_t)l*D_];
    }
    sred[jg][t & 63] = pacc;
    __syncthreads();
    if (t < 64)
        out[b*D_ + (bx & 15)*64 + t] = sred[0][t] + sred[1][t] + sred[2][t] + sred[3][t];
}

// ---------------------------------------------------------------------------
extern "C" void kernel_launch(void* const* d_in, const int* in_sizes, int n_in,
                              void* d_out, int out_size) {
    const float* mem = nullptr;
    const float* summ = nullptr;
    const float* w = nullptr;
    for (int i = 0; i < n_in; ++i) {
        if      (in_sizes[i] == B_*S_*D_) mem  = (const float*)d_in[i];
        else if (in_sizes[i] == L_*D_)    summ = (const float*)d_in[i];
        else if (in_sizes[i] == L_)       w    = (const float*)d_in[i];
    }
    static bool attrDone = false;
    if (!attrDone) {
        cudaFuncSetAttribute(kMain, cudaFuncAttributeMaxDynamicSharedMemorySize, SMEM_BYTES);
        attrDone = true;
    }
    kMain<<<GRID, THR, SMEM_BYTES>>>(mem, summ);
    kF<<<128, THR>>>(w, (float*)d_out);
}

// round 9
// speedup vs baseline: 1.0288x; 1.0288x over previous
#include <cuda_runtime.h>
#include <cstdint>

#define B_ 8
#define S_ 4096
#define D_ 1024
#define L_ 16

#define TR    16            // tile rows per stage
#define NT    16            // tiles per CTA -> 256 rows
#define CTAB  16
#define GRID  (B_*CTAB)     // 128
#define THR   512           // 16 warps
#define TP    1028
#define SP    1028
#define EP    20
#define RP    18

#define OFF_SU (2*TR*TP)               // 32896
#define OFF_ES (OFF_SU + L_*SP)        // 49344
#define OFF_RD (OFF_ES + L_*EP)        // 49664   (16 warps x 16 x RP)
#define OFF_ZB (OFF_RD + 16*L_*RP)     // 54272
#define SMEM_FLOATS (OFF_ZB + L_*RP)   // 54560
#define SMEM_BYTES  (SMEM_FLOATS*4)    // 218,240 B

__device__ float g_G[(size_t)GRID*L_*D_];   // per-CTA ctx partials (8 MB)
__device__ float g_cs[GRID*D_];             // per-CTA column sums
__device__ float g_z[GRID*L_];              // per-CTA sum(e-1)

__device__ __forceinline__ void cpa16(uint32_t saddr, const void* gaddr) {
    asm volatile("cp.async.ca.shared.global [%0], [%1], 16;\n" :: "r"(saddr), "l"(gaddr));
}
__device__ __forceinline__ void mma_tf32(float* c, const float* a, const float* b) {
    asm volatile(
        "mma.sync.aligned.m16n8k8.row.col.f32.tf32.tf32.f32 "
        "{%0,%1,%2,%3}, {%4,%5,%6,%7}, {%8,%9}, {%0,%1,%2,%3};\n"
        : "+f"(c[0]), "+f"(c[1]), "+f"(c[2]), "+f"(c[3])
        : "f"(a[0]), "f"(a[1]), "f"(a[2]), "f"(a[3]), "f"(b[0]), "f"(b[1]));
}

// ---------------------------------------------------------------------------
// Fused: per 16-row tile -> scores MMA (K split over 16 warps), exp,
// ctx MMA (d split over 16 warps), exact colsum. memory read exactly once.
// ---------------------------------------------------------------------------
__global__ void __launch_bounds__(THR, 1)
kMain(const float* __restrict__ mem, const float* __restrict__ summ) {
    extern __shared__ float sA[];
    const int t    = threadIdx.x;
    const int bx   = blockIdx.x;
    const int warp = t >> 5;
    const int lane = t & 31;
    const int g    = lane >> 2;
    const int tig  = lane & 3;
    const uint32_t sbase = (uint32_t)__cvta_generic_to_shared(sA);

    // summarizer -> padded smem
    for (int i = t; i < L_*D_; i += THR)
        sA[OFF_SU + (i >> 10)*SP + (i & 1023)] = summ[i];

    const int b    = bx >> 4;
    const int row0 = (bx & 15) * (TR*NT);
    const float* gbase = mem + ((size_t)b*S_ + row0)*D_;

    const int sr = t >> 5;            // staging row = warp
    const int sc = (t & 31) * 4;      // staging col

#define STAGE(i, buf) do {                                                     \
        const float* gp = gbase + ((size_t)((i)*TR + sr))*D_ + sc;             \
        uint32_t sp = sbase + 4u*((buf)*(TR*TP) + sr*TP + sc);                 \
        _Pragma("unroll")                                                      \
        for (int k = 0; k < 8; ++k) cpa16(sp + 4u*128*k, gp + 128*k);          \
        asm volatile("cp.async.commit_group;\n" ::: "memory");                 \
    } while (0)

    float gacc[8][4];
#pragma unroll
    for (int nt = 0; nt < 8; ++nt) { gacc[nt][0]=0.f; gacc[nt][1]=0.f; gacc[nt][2]=0.f; gacc[nt][3]=0.f; }
    float colacc[2] = {0.f, 0.f};
    float zacc = 0.f;
    const int lo = t >> 4, jo = t & 15;        // (l, s) for exp threads t<256

    STAGE(0, 0);

    for (int it = 0; it < NT; ++it) {
        if (it + 1 < NT) {
            STAGE(it + 1, (it + 1) & 1);
            asm volatile("cp.async.wait_group 1;\n" ::: "memory");
        } else {
            asm volatile("cp.async.wait_group 0;\n" ::: "memory");
        }
        __syncthreads();

        const float* tile = sA + (it & 1)*(TR*TP);

        // ---- scores MMA: warp owns k-slice [64w, 64w+64) ----
        {
            float s0[4] = {0.f,0.f,0.f,0.f}, s1[4] = {0.f,0.f,0.f,0.f};
            const int k0w = warp*64;
#pragma unroll
            for (int ks = 0; ks < 8; ++ks) {
                const int k0 = k0w + ks*8;
                float a[4];
                a[0] = sA[OFF_SU + g*SP     + k0 + tig];
                a[1] = sA[OFF_SU + (g+8)*SP + k0 + tig];
                a[2] = sA[OFF_SU + g*SP     + k0 + tig + 4];
                a[3] = sA[OFF_SU + (g+8)*SP + k0 + tig + 4];
                float b0[2], b1[2];
                b0[0] = tile[g*TP     + k0 + tig];
                b0[1] = tile[g*TP     + k0 + tig + 4];
                b1[0] = tile[(8+g)*TP + k0 + tig];
                b1[1] = tile[(8+g)*TP + k0 + tig + 4];
                mma_tf32(s0, a, b0);
                mma_tf32(s1, a, b1);
            }
            float* red = sA + OFF_RD + warp*(L_*RP);
            *(float2*)&red[g*RP     + 2*tig]     = make_float2(s0[0], s0[1]);
            *(float2*)&red[(g+8)*RP + 2*tig]     = make_float2(s0[2], s0[3]);
            *(float2*)&red[g*RP     + 8 + 2*tig] = make_float2(s1[0], s1[1]);
            *(float2*)&red[(g+8)*RP + 8 + 2*tig] = make_float2(s1[2], s1[3]);
        }

        // ---- exact column sums (independent of scores): 2 floats/thread ----
#pragma unroll
        for (int r = 0; r < TR; ++r) {
            float2 v = *(const float2*)&tile[r*TP + 2*t];
            colacc[0] += v.x; colacc[1] += v.y;
        }
        __syncthreads();

        // ---- exp: 256 threads, 16-way cross-warp k-reduction ----
        if (t < 256) {
            float scv = 0.f;
#pragma unroll
            for (int w = 0; w < 16; ++w) scv += sA[OFF_RD + w*(L_*RP) + lo*RP + jo];
            float em1 = __expf(scv * 0.03125f) - 1.0f;
            sA[OFF_ES + lo*EP + jo] = em1;
            zacc += em1;
        }
        __syncthreads();

        // ---- ctx MMA: warp owns d-slice [64w, 64w+64) ----
#pragma unroll
        for (int ksx = 0; ksx < 2; ++ksx) {
            const int k0 = ksx*8;
            float a[4];
            a[0] = sA[OFF_ES + g*EP     + k0 + tig];
            a[1] = sA[OFF_ES + (g+8)*EP + k0 + tig];
            a[2] = sA[OFF_ES + g*EP     + k0 + tig + 4];
            a[3] = sA[OFF_ES + (g+8)*EP + k0 + tig + 4];
#pragma unroll
            for (int nt = 0; nt < 8; ++nt) {
                const int n0 = warp*64 + nt*8;
                float bfr[2];
                bfr[0] = tile[(k0+tig)*TP   + n0 + g];
                bfr[1] = tile[(k0+tig+4)*TP + n0 + g];
                mma_tf32(gacc[nt], a, bfr);
            }
        }
        __syncthreads();    // all reads done before this buffer is restaged
    }
#undef STAGE

    // ---- epilogue ----
    *(float2*)&g_cs[bx*D_ + 2*t] = make_float2(colacc[0], colacc[1]);

    if (t < 256) sA[OFF_ZB + lo*RP + jo] = zacc;
    __syncthreads();
    if (t < L_) {
        float z = 0.f;
#pragma unroll
        for (int j = 0; j < 16; ++j) z += sA[OFF_ZB + t*RP + j];
        g_z[bx*L_ + t] = z;             // sum of (e-1); +S added in kF
    }

#pragma unroll
    for (int nt = 0; nt < 8; ++nt) {
        const int d0 = warp*64 + nt*8 + 2*tig;
        *(float2*)&g_G[((size_t)bx*L_ + g    )*D_ + d0] = make_float2(gacc[nt][0], gacc[nt][1]);
        *(float2*)&g_G[((size_t)bx*L_ + g + 8)*D_ + d0] = make_float2(gacc[nt][2], gacc[nt][3]);
    }
}

// ---------------------------------------------------------------------------
// Reduce: out[b,d] = C0*colsum[b,d] + sum_l c_bl * G[b,l,d]
// 256 blocks (8 b x 32 d-chunks of 32), 8 j-groups x 2 j each.
// ---------------------------------------------------------------------------
__global__ void __launch_bounds__(256, 2)
kF(const float* __restrict__ wproj, float* __restrict__ out) {
    const int t  = threadIdx.x;
    const int bx = blockIdx.x;
    const int b  = bx >> 5;
    const int dc = bx & 31;
    const int dd = t & 31;
    const int jg = t >> 5;                 // 0..7
    const int d  = dc*32 + dd;

    __shared__ float cl[L_];
    __shared__ float C0s;
    __shared__ float sred[8][33];

    if (t < L_) {
        float Z = (float)S_;
#pragma unroll
        for (int j = 0; j < CTAB; ++j) Z += g_z[(b*CTAB + j)*L_ + t];
        cl[t] = wproj[t] / Z;
    }
    __syncthreads();
    if (t == 0) {
        float c0 = 0.f;
#pragma unroll
        for (int l = 0; l < L_; ++l) c0 += cl[l];
        C0s = c0;
    }
    __syncthreads();

    float pacc = 0.f;
#pragma unroll
    for (int jj = 0; jj < 2; ++jj) {
        const int j = jg*2 + jj;
        pacc += C0s * g_cs[(b*CTAB + j)*D_ + d];
        const float* Gp = &g_G[((size_t)(b*CTAB + j))*L_*D_ + d];
#pragma unroll
        for (int l = 0; l < L_; ++l) pacc += cl[l] * Gp[(size_t)l*D_];
    }
    sred[jg][dd] = pacc;
    __syncthreads();
    if (t < 32) {
        float r = 0.f;
#pragma unroll
        for (int j = 0; j < 8; ++j) r += sred[j][t];
        out[b*D_ + dc*32 + t] = r;
    }
}

// ---------------------------------------------------------------------------
extern "C" void kernel_launch(void* const* d_in, const int* in_sizes, int n_in,
                              void* d_out, int out_size) {
    const float* mem = nullptr;
    const float* summ = nullptr;
    const float* w = nullptr;
    for (int i = 0; i < n_in; ++i) {
        if      (in_sizes[i] == B_*S_*D_) mem  = (const float*)d_in[i];
        else if (in_sizes[i] == L_*D_)    summ = (const float*)d_in[i];
        else if (in_sizes[i] == L_)       w    = (const float*)d_in[i];
    }
    static bool attrDone = false;
    if (!attrDone) {
        cudaFuncSetAttribute(kMain, cudaFuncAttributeMaxDynamicSharedMemorySize, SMEM_BYTES);
        attrDone = true;
    }
    kMain<<<GRID, THR, SMEM_BYTES>>>(mem, summ);
    kF<<<256, 256>>>(w, (float*)d_out);
}